// round 15
// baseline (speedup 1.0000x reference)
#include <cuda_runtime.h>
#include <cuda_bf16.h>

#define NN 50000
#define EE 800000
#define NB 6250            // dst>>3 buckets
#define PQ_BLOCKS ((NN + 127) / 128)
#define TID ((int)threadIdx.x)
typedef unsigned long long u64;
typedef unsigned int u32;
typedef unsigned short u16;

// ---------------- global scratch ----------------
__device__ float g_P[NN * 128];
__device__ float g_Q[NN * 128];
__device__ float g_agg[NN * 128];
__device__ int g_src[EE];
__device__ int g_dst[EE];
__device__ int g_bcnt[NB];   // zero-init at load; scan resets after reading (replay-safe)
__device__ int g_bcur[NB];
__device__ int g_s_src[EE];
__device__ int g_s_dst[EE];
__device__ int g_ord[EE];
// fragment-ordered bf16x2 weights (hi/lo split) for mma.sync B operands
#define W1F_U32 (2 * 2 * 16 * 32 * 2)     // edge Wm1c:  ver, kc(2),  t(16), lane(32), r(2)
#define W2F_U32 (2 * 8 * 16 * 32 * 2)     // edge Wm2:   ver, kc(8),  ...
#define WPQ_U32 (2 * 8 * 16 * 32 * 2)     // Wm1a / Wm1b
#define WU1_U32 (2 * 16 * 16 * 32 * 2)    // Wu1: [ver][ph*8+kc][t][lane][r]
#define WU2_U32 (2 * 8 * 16 * 32 * 2)     // Wu2
__device__ u32 g_W1f[W1F_U32];
__device__ u32 g_W2f[W2F_U32];
__device__ u32 g_WPf[WPQ_U32];
__device__ u32 g_WQf[WPQ_U32];
__device__ u32 g_WU1f[WU1_U32];
__device__ u32 g_WU2f[WU2_U32];

// ---------------- helpers ----------------
__device__ __forceinline__ u16 f2bf(float x) { u16 h; asm("cvt.rn.bf16.f32 %0, %1;" : "=h"(h) : "f"(x)); return h; }
__device__ __forceinline__ float bfhi2f(u16 h) { return __uint_as_float((u32)h << 16); }
__device__ __forceinline__ void red_add_v4(float* addr, float4 v) {
    asm volatile("red.global.add.v4.f32 [%0], {%1, %2, %3, %4};"
                 :: "l"(addr), "f"(v.x), "f"(v.y), "f"(v.z), "f"(v.w) : "memory");
}
__device__ __forceinline__ void split2(float x, float y, u32& hi, u32& lo) {
    u16 h0 = f2bf(x), h1 = f2bf(y);
    u16 l0 = f2bf(x - bfhi2f(h0)), l1 = f2bf(y - bfhi2f(h1));
    hi = (u32)h0 | ((u32)h1 << 16);
    lo = (u32)l0 | ((u32)l1 << 16);
}
__device__ __forceinline__ void mma16816(float c[4], const u32 a[4], u32 b0, u32 b1) {
    asm("mma.sync.aligned.m16n8k16.row.col.f32.bf16.bf16.f32 "
        "{%0,%1,%2,%3}, {%4,%5,%6,%7}, {%8,%9}, {%0,%1,%2,%3};"
        : "+f"(c[0]), "+f"(c[1]), "+f"(c[2]), "+f"(c[3])
        : "r"(a[0]), "r"(a[1]), "r"(a[2]), "r"(a[3]), "r"(b0), "r"(b1));
}
__device__ __forceinline__ void stage_u32(u32* dst, const u32* __restrict__ src, int n_u32) {
    float4* d = (float4*)dst; const float4* s = (const float4*)src;
    for (int i = TID; i < n_u32 / 4; i += 256) d[i] = s[i];
}

// ---------------- weight prep helper ----------------------------------------
__device__ __forceinline__ void prep_range(u32* dst, const float* __restrict__ Wsrc, int KC, int idx) {
    int r = idx & 1, l = (idx >> 1) & 31, t = (idx >> 6) & 15;
    int kc = (idx >> 10) % KC, ver = (idx >> 10) / KC;
    int k0 = kc * 16 + (l & 3) * 2 + r * 8;
    int n = t * 8 + (l >> 2);
    float v0 = Wsrc[k0 * 128 + n];
    float v1 = Wsrc[(k0 + 1) * 128 + n];
    u32 hi, lo; split2(v0, v1, hi, lo);
    dst[idx] = ver ? lo : hi;
}
#define PREP_TOTAL (W1F_U32 + W2F_U32 + 2 * WPQ_U32 + WU1_U32 + WU2_U32)

// ---------------- kernel 0: convert (dtype detect + histogram) + weight prep -
__global__ void convprep_kernel(const void* __restrict__ eidx,
                                const float* __restrict__ Wm1, const float* __restrict__ Wm2,
                                const float* __restrict__ Wu1, const float* __restrict__ Wu2) {
    __shared__ int s_ok;
    const long long* p64 = (const long long*)eidx;
    if (TID == 0) s_ok = 1;
    __syncthreads();
    if (TID < 64) {
        long long v = p64[TID];
        if (v < 0 || v >= NN) s_ok = 0;   // benign race: only writes 0
    }
    __syncthreads();
    int i = blockIdx.x * 256 + TID;
    if (i < EE) {
        int s, d;
        if (s_ok) {
            s = (int)p64[i];
            d = (int)p64[EE + i];
        } else {
            const int* p = (const int*)eidx;
            s = p[i];
            d = p[EE + i];
        }
        g_src[i] = s;
        g_dst[i] = d;
        atomicAdd(&g_bcnt[d >> 3], 1);
    }
    int gi = blockIdx.x * 256 + TID;
    if (gi < W1F_U32) { prep_range(g_W1f, Wm1 + 256 * 128, 2, gi); return; }
    gi -= W1F_U32;
    if (gi < W2F_U32) { prep_range(g_W2f, Wm2, 8, gi); return; }
    gi -= W2F_U32;
    if (gi < WPQ_U32) { prep_range(g_WPf, Wm1, 8, gi); return; }
    gi -= WPQ_U32;
    if (gi < WPQ_U32) { prep_range(g_WQf, Wm1 + 128 * 128, 8, gi); return; }
    gi -= WPQ_U32;
    if (gi < WU1_U32) { prep_range(g_WU1f, Wu1, 16, gi); return; }
    gi -= WU1_U32;
    if (gi < WU2_U32) { prep_range(g_WU2f, Wu2, 8, gi); return; }
}

// ---------------- kernel 1: exclusive scan (+ reset g_bcnt for replay) ------
__global__ void scan_kernel() {
    __shared__ int wsum[32];
    __shared__ int run;
    if (TID == 0) run = 0;
    __syncthreads();
    for (int c0 = 0; c0 < NB; c0 += 1024) {
        int i = c0 + TID;
        int v = (i < NB) ? g_bcnt[i] : 0;
        if (i < NB) g_bcnt[i] = 0;
        int x = v;
#pragma unroll
        for (int dd = 1; dd < 32; dd <<= 1) {
            int y = __shfl_up_sync(0xffffffffu, x, dd);
            if ((TID & 31) >= dd) x += y;
        }
        if ((TID & 31) == 31) wsum[TID >> 5] = x;
        __syncthreads();
        if (TID < 32) {
            int y = wsum[TID];
#pragma unroll
            for (int dd = 1; dd < 32; dd <<= 1) {
                int z = __shfl_up_sync(0xffffffffu, y, dd);
                if (TID >= dd) y += z;
            }
            wsum[TID] = y;
        }
        __syncthreads();
        int excl = x - v + ((TID >= 32) ? wsum[(TID >> 5) - 1] : 0);
        if (i < NB) g_bcur[i] = run + excl;
        __syncthreads();
        if (TID == 0) run += wsum[31];
        __syncthreads();
    }
}

// ---------------- kernel 2: pq (P/Q GEMMs + agg zero) fused with scatter ----
#define PQ2_SMEM (WPQ_U32 * 4)
__global__ void __launch_bounds__(256, 2)
pq_scatter_kernel(const float* __restrict__ h) {
    {
        int i = blockIdx.x * 256 + TID;
        if (i < EE) {
            int s = g_src[i], d = g_dst[i];
            int pos = atomicAdd(&g_bcur[d >> 3], 1);
            g_s_src[pos] = s;
            g_s_dst[pos] = d;
            g_ord[pos] = i;
        }
    }
    if (blockIdx.x >= PQ_BLOCKS) return;

    extern __shared__ u32 smw[];
    int w = TID >> 5, l = TID & 31;
    int base = blockIdx.x * 128;
    int g = l >> 2, q = (l & 3) * 2;
    int r0 = base + w * 16 + g, r1 = r0 + 8;
    bool v0 = r0 < NN, v1 = r1 < NN;

    for (int s2 = TID; s2 < 128 * 32; s2 += 256) {
        int node = base + (s2 >> 5);
        if (node < NN)
            reinterpret_cast<float4*>(g_agg)[(size_t)node * 32 + (s2 & 31)] =
                make_float4(0.f, 0.f, 0.f, 0.f);
    }

    u32 Ah[8][4], Al[8][4];
    {
        const float* ra = h + (size_t)r0 * 128;
        const float* rb = h + (size_t)r1 * 128;
        float2 z = make_float2(0.f, 0.f);
#pragma unroll
        for (int kc = 0; kc < 8; ++kc) {
            float2 a0 = v0 ? *(const float2*)(ra + kc * 16 + q) : z;
            float2 a1 = v1 ? *(const float2*)(rb + kc * 16 + q) : z;
            float2 a2 = v0 ? *(const float2*)(ra + kc * 16 + q + 8) : z;
            float2 a3 = v1 ? *(const float2*)(rb + kc * 16 + q + 8) : z;
            split2(a0.x, a0.y, Ah[kc][0], Al[kc][0]);
            split2(a1.x, a1.y, Ah[kc][1], Al[kc][1]);
            split2(a2.x, a2.y, Ah[kc][2], Al[kc][2]);
            split2(a3.x, a3.y, Ah[kc][3], Al[kc][3]);
        }
    }

#pragma unroll 1
    for (int m = 0; m < 2; ++m) {
        if (m) __syncthreads();
        stage_u32(smw, m ? g_WQf : g_WPf, WPQ_U32);
        __syncthreads();
        float* dst = m ? g_Q : g_P;
#pragma unroll
        for (int hf = 0; hf < 2; ++hf) {
            float C[8][4];
#pragma unroll
            for (int t = 0; t < 8; ++t) { C[t][0] = C[t][1] = C[t][2] = C[t][3] = 0.f; }
#pragma unroll
            for (int kc = 0; kc < 8; ++kc)
#pragma unroll
                for (int t = 0; t < 8; ++t) {
                    int tt = hf * 8 + t;
                    uint2 bv = *(const uint2*)(smw + (((kc * 16 + tt) * 32 + l) * 2));
                    mma16816(C[t], Ah[kc], bv.x, bv.y);
                    mma16816(C[t], Al[kc], bv.x, bv.y);
                }
#pragma unroll
            for (int kc = 0; kc < 8; ++kc)
#pragma unroll
                for (int t = 0; t < 8; ++t) {
                    int tt = hf * 8 + t;
                    uint2 bv = *(const uint2*)(smw + ((((8 + kc) * 16 + tt) * 32 + l) * 2));
                    mma16816(C[t], Ah[kc], bv.x, bv.y);
                }
#pragma unroll
            for (int t = 0; t < 8; ++t) {
                int c = hf * 64 + t * 8 + q;
                if (v0) *(float2*)(dst + (size_t)r0 * 128 + c) = make_float2(C[t][0], C[t][1]);
                if (v1) *(float2*)(dst + (size_t)r1 * 128 + c) = make_float2(C[t][2], C[t][3]);
            }
        }
    }
}

// ---------------- kernel 3: edge (mma.sync bf16x3, split-K warp pairs) ------
// 256 edges/block (2 subs of 128). Warp: rows p*32..+32 (mt=2), H = col/K-half.
// GEMM0 out cols = H*64..+64 == GEMM1 K-half -> register C->A identity holds.
// GEMM1 partials exchanged through smem in fragment layout (conflict-free),
// H0 adds + bm2 + relu + scatters. Quarter (32-col) granularity, 16 KB buffer.
#define EDGE_SMEM_C ((W1F_U32 + W2F_U32 + 4096 + 384) * 4)
__global__ void __launch_bounds__(256, 2)
edge_kernel(const float* __restrict__ edge_attr,
            const float* __restrict__ bm1, const float* __restrict__ bm2) {
    extern __shared__ u32 smu[];
    u32* W1s = smu;
    u32* W2s = W1s + W1F_U32;
    float* part = (float*)(W2s + W2F_U32);   // 4096 floats
    int* ssrc = (int*)(part + 4096);         // 128
    int* sdst = ssrc + 128;                  // 128
    int* sord = sdst + 128;                  // 128

    int w = TID >> 5, l = TID & 31;
    int p = w & 3, H = w >> 2;
    int g = l >> 2, q = (l & 3) * 2;
    int rb = p * 32;

    stage_u32(W1s, g_W1f, W1F_U32);
    stage_u32(W2s, g_W2f, W2F_U32);

#pragma unroll 1
    for (int sub = 0; sub < 2; ++sub) {
        int base = blockIdx.x * 256 + sub * 128;
        if (sub) __syncthreads();
        if (TID < 128) {
            ssrc[TID] = g_s_src[base + TID];
            sdst[TID] = g_s_dst[base + TID];
            sord[TID] = g_ord[base + TID];
        }
        __syncthreads();

        int rA0 = rb + g, rB0 = rA0 + 8;
        int rA1 = rb + 16 + g, rB1 = rA1 + 8;

        // E fragments (full k=32), hi/lo, for both m-tiles
        u32 Eh[2][2][4], El[2][2][4];
        {
            const float* eA0 = edge_attr + (size_t)sord[rA0] * 32;
            const float* eB0 = edge_attr + (size_t)sord[rB0] * 32;
            const float* eA1 = edge_attr + (size_t)sord[rA1] * 32;
            const float* eB1 = edge_attr + (size_t)sord[rB1] * 32;
#pragma unroll
            for (int kc = 0; kc < 2; ++kc) {
                int k0 = kc * 16 + q;
                float2 f0 = *(const float2*)(eA0 + k0);
                float2 f1 = *(const float2*)(eB0 + k0);
                float2 f2 = *(const float2*)(eA0 + k0 + 8);
                float2 f3 = *(const float2*)(eB0 + k0 + 8);
                split2(f0.x, f0.y, Eh[0][kc][0], El[0][kc][0]);
                split2(f1.x, f1.y, Eh[0][kc][1], El[0][kc][1]);
                split2(f2.x, f2.y, Eh[0][kc][2], El[0][kc][2]);
                split2(f3.x, f3.y, Eh[0][kc][3], El[0][kc][3]);
                f0 = *(const float2*)(eA1 + k0);
                f1 = *(const float2*)(eB1 + k0);
                f2 = *(const float2*)(eA1 + k0 + 8);
                f3 = *(const float2*)(eB1 + k0 + 8);
                split2(f0.x, f0.y, Eh[1][kc][0], El[1][kc][0]);
                split2(f1.x, f1.y, Eh[1][kc][1], El[1][kc][1]);
                split2(f2.x, f2.y, Eh[1][kc][2], El[1][kc][2]);
                split2(f3.x, f3.y, Eh[1][kc][3], El[1][kc][3]);
            }
        }

        // C init: x_pre = P[src]+Q[dst]+bm1 for cols H*64 + t*8
        float C[2][8][4];
        int dA0 = sdst[rA0], dB0 = sdst[rB0], dA1 = sdst[rA1], dB1 = sdst[rB1];
        {
            const float* PA0 = g_P + (size_t)ssrc[rA0] * 128 + H * 64;
            const float* PB0 = g_P + (size_t)ssrc[rB0] * 128 + H * 64;
            const float* PA1 = g_P + (size_t)ssrc[rA1] * 128 + H * 64;
            const float* PB1 = g_P + (size_t)ssrc[rB1] * 128 + H * 64;
            const float* QA0 = g_Q + (size_t)dA0 * 128 + H * 64;
            const float* QB0 = g_Q + (size_t)dB0 * 128 + H * 64;
            const float* QA1 = g_Q + (size_t)dA1 * 128 + H * 64;
            const float* QB1 = g_Q + (size_t)dB1 * 128 + H * 64;
            const float* bh = bm1 + H * 64;
#pragma unroll
            for (int t = 0; t < 8; ++t) {
                int c = t * 8 + q;
                float2 b = *(const float2*)(bh + c);
                float2 pa = *(const float2*)(PA0 + c), qa = *(const float2*)(QA0 + c);
                C[0][t][0] = pa.x + qa.x + b.x; C[0][t][1] = pa.y + qa.y + b.y;
                pa = *(const float2*)(PB0 + c); qa = *(const float2*)(QB0 + c);
                C[0][t][2] = pa.x + qa.x + b.x; C[0][t][3] = pa.y + qa.y + b.y;
                pa = *(const float2*)(PA1 + c); qa = *(const float2*)(QA1 + c);
                C[1][t][0] = pa.x + qa.x + b.x; C[1][t][1] = pa.y + qa.y + b.y;
                pa = *(const float2*)(PB1 + c); qa = *(const float2*)(QB1 + c);
                C[1][t][2] = pa.x + qa.x + b.x; C[1][t][3] = pa.y + qa.y + b.y;
            }
        }

        // GEMM0: B cols = H*8 + t; each load feeds both m-tiles
#pragma unroll
        for (int kc = 0; kc < 2; ++kc)
#pragma unroll
            for (int t = 0; t < 8; ++t) {
                uint2 bv = *(const uint2*)(W1s + (((kc * 16 + H * 8 + t) * 32 + l) * 2));
                mma16816(C[0][t], Eh[0][kc], bv.x, bv.y);
                mma16816(C[0][t], El[0][kc], bv.x, bv.y);
                mma16816(C[1][t], Eh[1][kc], bv.x, bv.y);
                mma16816(C[1][t], El[1][kc], bv.x, bv.y);
            }
#pragma unroll
        for (int kc = 0; kc < 2; ++kc)
#pragma unroll
            for (int t = 0; t < 8; ++t) {
                uint2 bv = *(const uint2*)(W1s + ((((2 + kc) * 16 + H * 8 + t) * 32 + l) * 2));
                mma16816(C[0][t], Eh[0][kc], bv.x, bv.y);
                mma16816(C[1][t], Eh[1][kc], bv.x, bv.y);
            }

        // epilogue: relu -> X A-fragments for K-half H (identity map per mt)
        u32 Ah[2][4][4], Al[2][4][4];
#pragma unroll
        for (int mt = 0; mt < 2; ++mt)
#pragma unroll
            for (int kc = 0; kc < 4; ++kc) {
                split2(fmaxf(C[mt][2 * kc][0], 0.f),     fmaxf(C[mt][2 * kc][1], 0.f),     Ah[mt][kc][0], Al[mt][kc][0]);
                split2(fmaxf(C[mt][2 * kc][2], 0.f),     fmaxf(C[mt][2 * kc][3], 0.f),     Ah[mt][kc][1], Al[mt][kc][1]);
                split2(fmaxf(C[mt][2 * kc + 1][0], 0.f), fmaxf(C[mt][2 * kc + 1][1], 0.f), Ah[mt][kc][2], Al[mt][kc][2]);
                split2(fmaxf(C[mt][2 * kc + 1][2], 0.f), fmaxf(C[mt][2 * kc + 1][3], 0.f), Ah[mt][kc][3], Al[mt][kc][3]);
            }

        float* aggA0 = g_agg + (size_t)dA0 * 128;
        float* aggB0 = g_agg + (size_t)dB0 * 128;
        float* aggA1 = g_agg + (size_t)dA1 * 128;
        float* aggB1 = g_agg + (size_t)dB1 * 128;

        // GEMM1 in 32-col quarters; K split across H pairs, reduce via smem
#pragma unroll 1
        for (int qf = 0; qf < 4; ++qf) {
            float C2[2][4][4];
#pragma unroll
            for (int t = 0; t < 4; ++t) {
                float2 b = make_float2(0.f, 0.f);
                if (H == 0) b = *(const float2*)(bm2 + qf * 32 + t * 8 + q);
                C2[0][t][0] = b.x; C2[0][t][1] = b.y; C2[0][t][2] = b.x; C2[0][t][3] = b.y;
                C2[1][t][0] = b.x; C2[1][t][1] = b.y; C2[1][t][2] = b.x; C2[1][t][3] = b.y;
            }
#pragma unroll
            for (int kc = 0; kc < 4; ++kc) {
                int kcg = H * 4 + kc;
#pragma unroll
                for (int t = 0; t < 4; ++t) {
                    int tt = qf * 4 + t;
                    uint2 bv = *(const uint2*)(W2s + (((kcg * 16 + tt) * 32 + l) * 2));
                    mma16816(C2[0][t], Ah[0][kc], bv.x, bv.y);
                    mma16816(C2[0][t], Al[0][kc], bv.x, bv.y);
                    mma16816(C2[1][t], Ah[1][kc], bv.x, bv.y);
                    mma16816(C2[1][t], Al[1][kc], bv.x, bv.y);
                }
            }
#pragma unroll
            for (int kc = 0; kc < 4; ++kc) {
                int kcg = H * 4 + kc;
#pragma unroll
                for (int t = 0; t < 4; ++t) {
                    int tt = qf * 4 + t;
                    uint2 bv = *(const uint2*)(W2s + ((((8 + kcg) * 16 + tt) * 32 + l) * 2));
                    mma16816(C2[0][t], Ah[0][kc], bv.x, bv.y);
                    mma16816(C2[1][t], Ah[1][kc], bv.x, bv.y);
                }
            }
            if (H == 1) {
#pragma unroll
                for (int mt = 0; mt < 2; ++mt)
#pragma unroll
                    for (int t = 0; t < 4; ++t)
                        *(float4*)(part + ((((p * 2 + mt) * 4 + t) * 32 + l) * 4)) =
                            make_float4(C2[mt][t][0], C2[mt][t][1], C2[mt][t][2], C2[mt][t][3]);
            }
            __syncthreads();
            if (H == 0) {
#pragma unroll
                for (int mt = 0; mt < 2; ++mt)
#pragma unroll
                    for (int t = 0; t < 4; ++t) {
                        float4 o = *(const float4*)(part + ((((p * 2 + mt) * 4 + t) * 32 + l) * 4));
                        float a0 = fmaxf(C2[mt][t][0] + o.x, 0.f);
                        float a1 = fmaxf(C2[mt][t][1] + o.y, 0.f);
                        float a2 = fmaxf(C2[mt][t][2] + o.z, 0.f);
                        float a3 = fmaxf(C2[mt][t][3] + o.w, 0.f);
                        float p0 = __shfl_xor_sync(0xffffffffu, a0, 1);
                        float p1 = __shfl_xor_sync(0xffffffffu, a1, 1);
                        float p2 = __shfl_xor_sync(0xffffffffu, a2, 1);
                        float p3 = __shfl_xor_sync(0xffffffffu, a3, 1);
                        if (!(l & 1)) {
                            int c = qf * 32 + t * 8 + q;
                            float* gA = mt ? aggA1 : aggA0;
                            float* gB = mt ? aggB1 : aggB0;
                            red_add_v4(gA + c, make_float4(a0, a1, p0, p1));
                            red_add_v4(gB + c, make_float4(a2, a3, p2, p3));
                        }
                    }
            }
            __syncthreads();
        }
    }
}

// ---------------- kernel 4: update (mma.sync, 64KB smem, occ 2) -------------
#define UPD2_SMEM (16384 * 4)
__global__ void __launch_bounds__(256, 2)
update_kernel(const float* __restrict__ h,
              const float* __restrict__ bu1, const float* __restrict__ bu2,
              float* __restrict__ out) {
    extern __shared__ u32 smw[];
    int w = TID >> 5, l = TID & 31;
    int base = blockIdx.x * 128;
    int g = l >> 2, q = (l & 3) * 2;
    int r0 = base + w * 16 + g, r1 = r0 + 8;
    bool v0 = r0 < NN, v1 = r1 < NN;

    float C[16][4];
#pragma unroll
    for (int t = 0; t < 16; ++t) {
        float2 b = *(const float2*)(bu1 + t * 8 + q);
        C[t][0] = b.x; C[t][1] = b.y; C[t][2] = b.x; C[t][3] = b.y;
    }

    stage_u32(smw, g_WU1f, 16384);
    __syncthreads();
#pragma unroll 1
    for (int ph = 0; ph < 2; ++ph) {
        const float* src = ph ? g_agg : h;
        u32 Ahp[8][4], Alp[8][4];
        {
            const float* ra = src + (size_t)r0 * 128;
            const float* rb = src + (size_t)r1 * 128;
            float2 z = make_float2(0.f, 0.f);
#pragma unroll
            for (int kc = 0; kc < 8; ++kc) {
                float2 a0 = v0 ? *(const float2*)(ra + kc * 16 + q) : z;
                float2 a1 = v1 ? *(const float2*)(rb + kc * 16 + q) : z;
                float2 a2 = v0 ? *(const float2*)(ra + kc * 16 + q + 8) : z;
                float2 a3 = v1 ? *(const float2*)(rb + kc * 16 + q + 8) : z;
                split2(a0.x, a0.y, Ahp[kc][0], Alp[kc][0]);
                split2(a1.x, a1.y, Ahp[kc][1], Alp[kc][1]);
                split2(a2.x, a2.y, Ahp[kc][2], Alp[kc][2]);
                split2(a3.x, a3.y, Ahp[kc][3], Alp[kc][3]);
            }
        }
#pragma unroll
        for (int kc = 0; kc < 8; ++kc)
#pragma unroll
            for (int t = 0; t < 16; ++t) {
                uint2 bv = *(const uint2*)(smw + ((((ph * 8 + kc) * 16 + t) * 32 + l) * 2));
                mma16816(C[t], Ahp[kc], bv.x, bv.y);
                mma16816(C[t], Alp[kc], bv.x, bv.y);
            }
    }
    __syncthreads();
    stage_u32(smw, g_WU1f + 16384, 16384);
    __syncthreads();
#pragma unroll 1
    for (int ph = 0; ph < 2; ++ph) {
        const float* src = ph ? g_agg : h;
        u32 Ahp[8][4];
        {
            const float* ra = src + (size_t)r0 * 128;
            const float* rb = src + (size_t)r1 * 128;
            float2 z = make_float2(0.f, 0.f);
#pragma unroll
            for (int kc = 0; kc < 8; ++kc) {
                float2 a0 = v0 ? *(const float2*)(ra + kc * 16 + q) : z;
                float2 a1 = v1 ? *(const float2*)(rb + kc * 16 + q) : z;
                float2 a2 = v0 ? *(const float2*)(ra + kc * 16 + q + 8) : z;
                float2 a3 = v1 ? *(const float2*)(rb + kc * 16 + q + 8) : z;
                u16 h0 = f2bf(a0.x), h1 = f2bf(a0.y);
                Ahp[kc][0] = (u32)h0 | ((u32)h1 << 16);
                h0 = f2bf(a1.x); h1 = f2bf(a1.y);
                Ahp[kc][1] = (u32)h0 | ((u32)h1 << 16);
                h0 = f2bf(a2.x); h1 = f2bf(a2.y);
                Ahp[kc][2] = (u32)h0 | ((u32)h1 << 16);
                h0 = f2bf(a3.x); h1 = f2bf(a3.y);
                Ahp[kc][3] = (u32)h0 | ((u32)h1 << 16);
            }
        }
#pragma unroll
        for (int kc = 0; kc < 8; ++kc)
#pragma unroll
            for (int t = 0; t < 16; ++t) {
                uint2 bv = *(const uint2*)(smw + ((((ph * 8 + kc) * 16 + t) * 32 + l) * 2));
                mma16816(C[t], Ahp[kc], bv.x, bv.y);
            }
    }

    u32 Ah[8][4], Al[8][4];
#pragma unroll
    for (int kc = 0; kc < 8; ++kc) {
        split2(fmaxf(C[2 * kc][0], 0.f),     fmaxf(C[2 * kc][1], 0.f),     Ah[kc][0], Al[kc][0]);
        split2(fmaxf(C[2 * kc][2], 0.f),     fmaxf(C[2 * kc][3], 0.f),     Ah[kc][1], Al[kc][1]);
        split2(fmaxf(C[2 * kc + 1][0], 0.f), fmaxf(C[2 * kc + 1][1], 0.f), Ah[kc][2], Al[kc][2]);
        split2(fmaxf(C[2 * kc + 1][2], 0.f), fmaxf(C[2 * kc + 1][3], 0.f), Ah[kc][3], Al[kc][3]);
    }
    __syncthreads();
    stage_u32(smw, g_WU2f, WU2_U32);
    __syncthreads();

#pragma unroll
    for (int hf = 0; hf < 2; ++hf) {
        float C2[8][4];
#pragma unroll
        for (int t = 0; t < 8; ++t) {
            float2 b = *(const float2*)(bu2 + hf * 64 + t * 8 + q);
            C2[t][0] = b.x; C2[t][1] = b.y; C2[t][2] = b.x; C2[t][3] = b.y;
        }
#pragma unroll
        for (int kc = 0; kc < 8; ++kc)
#pragma unroll
            for (int t = 0; t < 8; ++t) {
                int tt = hf * 8 + t;
                uint2 bv = *(const uint2*)(smw + (((kc * 16 + tt) * 32 + l) * 2));
                mma16816(C2[t], Ah[kc], bv.x, bv.y);
                mma16816(C2[t], Al[kc], bv.x, bv.y);
            }
#pragma unroll
        for (int kc = 0; kc < 8; ++kc)
#pragma unroll
            for (int t = 0; t < 8; ++t) {
                int tt = hf * 8 + t;
                uint2 bv = *(const uint2*)(smw + ((((8 + kc) * 16 + tt) * 32 + l) * 2));
                mma16816(C2[t], Ah[kc], bv.x, bv.y);
            }
#pragma unroll
        for (int t = 0; t < 8; ++t) {
            int c = hf * 64 + t * 8 + q;
            if (v0) {
                float2 hh = *(const float2*)(h + (size_t)r0 * 128 + c);
                *(float2*)(out + (size_t)r0 * 128 + c) = make_float2(hh.x + C2[t][0], hh.y + C2[t][1]);
            }
            if (v1) {
                float2 hh = *(const float2*)(h + (size_t)r1 * 128 + c);
                *(float2*)(out + (size_t)r1 * 128 + c) = make_float2(hh.x + C2[t][2], hh.y + C2[t][3]);
            }
        }
    }
}

// ---------------------------------------------------------------------------
extern "C" void kernel_launch(void* const* d_in, const int* in_sizes, int n_in,
                              void* d_out, int out_size) {
    const float* h         = (const float*)d_in[0];
    const float* edge_attr = (const float*)d_in[1];
    const float* Wm1       = (const float*)d_in[2];
    const float* bm1       = (const float*)d_in[3];
    const float* Wm2       = (const float*)d_in[4];
    const float* bm2       = (const float*)d_in[5];
    const float* Wu1       = (const float*)d_in[6];
    const float* bu1       = (const float*)d_in[7];
    const float* Wu2       = (const float*)d_in[8];
    const float* bu2       = (const float*)d_in[9];
    const void*  eidx      = (const void*)d_in[10];
    float* out             = (float*)d_out;

    cudaFuncSetAttribute(pq_scatter_kernel, cudaFuncAttributeMaxDynamicSharedMemorySize, PQ2_SMEM);
    cudaFuncSetAttribute(edge_kernel,       cudaFuncAttributeMaxDynamicSharedMemorySize, EDGE_SMEM_C);
    cudaFuncSetAttribute(update_kernel,     cudaFuncAttributeMaxDynamicSharedMemorySize, UPD2_SMEM);

    convprep_kernel<<<(EE + 255) / 256, 256>>>(eidx, Wm1, Wm2, Wu1, Wu2);  // idx 0
    scan_kernel<<<1, 1024>>>();                                            // idx 1
    pq_scatter_kernel<<<(EE + 255) / 256, 256, PQ2_SMEM>>>(h);             // idx 2
    edge_kernel<<<EE / 256, 256, EDGE_SMEM_C>>>(edge_attr, bm1, bm2);      // idx 3 (profiled)
    update_kernel<<<(NN + 127) / 128, 256, UPD2_SMEM>>>(h, bu1, bu2, out); // idx 4
}

// round 16
// speedup vs baseline: 1.1561x; 1.1561x over previous
#include <cuda_runtime.h>
#include <cuda_bf16.h>

#define NN 50000
#define EE 800000
#define NB 6250            // dst>>3 buckets
#define PQ_BLOCKS ((NN + 127) / 128)
#define TID ((int)threadIdx.x)
typedef unsigned long long u64;
typedef unsigned int u32;
typedef unsigned short u16;

// ---------------- global scratch ----------------
__device__ float g_P[NN * 128];
__device__ float g_Q[NN * 128];
__device__ float g_agg[NN * 128];
__device__ int g_src[EE];
__device__ int g_dst[EE];
__device__ int g_bcnt[NB];   // zero-init at load; scan resets after reading (replay-safe)
__device__ int g_bcur[NB];
__device__ int g_s_src[EE];
__device__ int g_s_dst[EE];
__device__ int g_ord[EE];
// fragment-ordered bf16x2 weights (hi/lo split) for mma.sync B operands
#define W1F_U32 (2 * 2 * 16 * 32 * 2)     // edge Wm1c:  ver, kc(2),  t(16), lane(32), r(2)
#define W2F_U32 (2 * 8 * 16 * 32 * 2)     // edge Wm2:   ver, kc(8),  ...
#define WPQ_U32 (2 * 8 * 16 * 32 * 2)     // Wm1a / Wm1b
#define WU1_U32 (2 * 16 * 16 * 32 * 2)    // Wu1: [ver][ph*8+kc][t][lane][r]
#define WU2_U32 (2 * 8 * 16 * 32 * 2)     // Wu2
__device__ u32 g_W1f[W1F_U32];
__device__ u32 g_W2f[W2F_U32];
__device__ u32 g_WPf[WPQ_U32];
__device__ u32 g_WQf[WPQ_U32];
__device__ u32 g_WU1f[WU1_U32];
__device__ u32 g_WU2f[WU2_U32];

// ---------------- helpers ----------------
__device__ __forceinline__ u16 f2bf(float x) { u16 h; asm("cvt.rn.bf16.f32 %0, %1;" : "=h"(h) : "f"(x)); return h; }
__device__ __forceinline__ float bfhi2f(u16 h) { return __uint_as_float((u32)h << 16); }
__device__ __forceinline__ void red_add_v4(float* addr, float4 v) {
    asm volatile("red.global.add.v4.f32 [%0], {%1, %2, %3, %4};"
                 :: "l"(addr), "f"(v.x), "f"(v.y), "f"(v.z), "f"(v.w) : "memory");
}
__device__ __forceinline__ void split2(float x, float y, u32& hi, u32& lo) {
    u16 h0 = f2bf(x), h1 = f2bf(y);
    u16 l0 = f2bf(x - bfhi2f(h0)), l1 = f2bf(y - bfhi2f(h1));
    hi = (u32)h0 | ((u32)h1 << 16);
    lo = (u32)l0 | ((u32)l1 << 16);
}
__device__ __forceinline__ void mma16816(float c[4], const u32 a[4], u32 b0, u32 b1) {
    asm("mma.sync.aligned.m16n8k16.row.col.f32.bf16.bf16.f32 "
        "{%0,%1,%2,%3}, {%4,%5,%6,%7}, {%8,%9}, {%0,%1,%2,%3};"
        : "+f"(c[0]), "+f"(c[1]), "+f"(c[2]), "+f"(c[3])
        : "r"(a[0]), "r"(a[1]), "r"(a[2]), "r"(a[3]), "r"(b0), "r"(b1));
}
__device__ __forceinline__ void stage_u32(u32* dst, const u32* __restrict__ src, int n_u32) {
    float4* d = (float4*)dst; const float4* s = (const float4*)src;
    for (int i = TID; i < n_u32 / 4; i += 256) d[i] = s[i];
}

// ---------------- weight prep helper ----------------------------------------
__device__ __forceinline__ void prep_range(u32* dst, const float* __restrict__ Wsrc, int KC, int idx) {
    int r = idx & 1, l = (idx >> 1) & 31, t = (idx >> 6) & 15;
    int kc = (idx >> 10) % KC, ver = (idx >> 10) / KC;
    int k0 = kc * 16 + (l & 3) * 2 + r * 8;
    int n = t * 8 + (l >> 2);
    float v0 = Wsrc[k0 * 128 + n];
    float v1 = Wsrc[(k0 + 1) * 128 + n];
    u32 hi, lo; split2(v0, v1, hi, lo);
    dst[idx] = ver ? lo : hi;
}
#define PREP_TOTAL (W1F_U32 + W2F_U32 + 2 * WPQ_U32 + WU1_U32 + WU2_U32)

// ---------------- kernel 0: convert (dtype detect + histogram) + weight prep -
__global__ void convprep_kernel(const void* __restrict__ eidx,
                                const float* __restrict__ Wm1, const float* __restrict__ Wm2,
                                const float* __restrict__ Wu1, const float* __restrict__ Wu2) {
    __shared__ int s_ok;
    const long long* p64 = (const long long*)eidx;
    if (TID == 0) s_ok = 1;
    __syncthreads();
    if (TID < 64) {
        long long v = p64[TID];
        if (v < 0 || v >= NN) s_ok = 0;   // benign race: only writes 0
    }
    __syncthreads();
    int i = blockIdx.x * 256 + TID;
    if (i < EE) {
        int s, d;
        if (s_ok) {
            s = (int)p64[i];
            d = (int)p64[EE + i];
        } else {
            const int* p = (const int*)eidx;
            s = p[i];
            d = p[EE + i];
        }
        g_src[i] = s;
        g_dst[i] = d;
        atomicAdd(&g_bcnt[d >> 3], 1);
    }
    int gi = blockIdx.x * 256 + TID;
    if (gi < W1F_U32) { prep_range(g_W1f, Wm1 + 256 * 128, 2, gi); return; }
    gi -= W1F_U32;
    if (gi < W2F_U32) { prep_range(g_W2f, Wm2, 8, gi); return; }
    gi -= W2F_U32;
    if (gi < WPQ_U32) { prep_range(g_WPf, Wm1, 8, gi); return; }
    gi -= WPQ_U32;
    if (gi < WPQ_U32) { prep_range(g_WQf, Wm1 + 128 * 128, 8, gi); return; }
    gi -= WPQ_U32;
    if (gi < WU1_U32) { prep_range(g_WU1f, Wu1, 16, gi); return; }
    gi -= WU1_U32;
    if (gi < WU2_U32) { prep_range(g_WU2f, Wu2, 8, gi); return; }
}

// ---------------- kernel 1: exclusive scan (+ reset g_bcnt for replay) ------
__global__ void scan_kernel() {
    __shared__ int wsum[32];
    __shared__ int run;
    if (TID == 0) run = 0;
    __syncthreads();
    for (int c0 = 0; c0 < NB; c0 += 1024) {
        int i = c0 + TID;
        int v = (i < NB) ? g_bcnt[i] : 0;
        if (i < NB) g_bcnt[i] = 0;
        int x = v;
#pragma unroll
        for (int dd = 1; dd < 32; dd <<= 1) {
            int y = __shfl_up_sync(0xffffffffu, x, dd);
            if ((TID & 31) >= dd) x += y;
        }
        if ((TID & 31) == 31) wsum[TID >> 5] = x;
        __syncthreads();
        if (TID < 32) {
            int y = wsum[TID];
#pragma unroll
            for (int dd = 1; dd < 32; dd <<= 1) {
                int z = __shfl_up_sync(0xffffffffu, y, dd);
                if (TID >= dd) y += z;
            }
            wsum[TID] = y;
        }
        __syncthreads();
        int excl = x - v + ((TID >= 32) ? wsum[(TID >> 5) - 1] : 0);
        if (i < NB) g_bcur[i] = run + excl;
        __syncthreads();
        if (TID == 0) run += wsum[31];
        __syncthreads();
    }
}

// ---------------- kernel 2: pq (P/Q GEMMs + agg zero) fused with scatter ----
#define PQ2_SMEM (WPQ_U32 * 4)
__global__ void __launch_bounds__(256, 2)
pq_scatter_kernel(const float* __restrict__ h) {
    {
        int i = blockIdx.x * 256 + TID;
        if (i < EE) {
            int s = g_src[i], d = g_dst[i];
            int pos = atomicAdd(&g_bcur[d >> 3], 1);
            g_s_src[pos] = s;
            g_s_dst[pos] = d;
            g_ord[pos] = i;
        }
    }
    if (blockIdx.x >= PQ_BLOCKS) return;

    extern __shared__ u32 smw[];
    int w = TID >> 5, l = TID & 31;
    int base = blockIdx.x * 128;
    int g = l >> 2, q = (l & 3) * 2;
    int r0 = base + w * 16 + g, r1 = r0 + 8;
    bool v0 = r0 < NN, v1 = r1 < NN;

    for (int s2 = TID; s2 < 128 * 32; s2 += 256) {
        int node = base + (s2 >> 5);
        if (node < NN)
            reinterpret_cast<float4*>(g_agg)[(size_t)node * 32 + (s2 & 31)] =
                make_float4(0.f, 0.f, 0.f, 0.f);
    }

    u32 Ah[8][4], Al[8][4];
    {
        const float* ra = h + (size_t)r0 * 128;
        const float* rb = h + (size_t)r1 * 128;
        float2 z = make_float2(0.f, 0.f);
#pragma unroll
        for (int kc = 0; kc < 8; ++kc) {
            float2 a0 = v0 ? *(const float2*)(ra + kc * 16 + q) : z;
            float2 a1 = v1 ? *(const float2*)(rb + kc * 16 + q) : z;
            float2 a2 = v0 ? *(const float2*)(ra + kc * 16 + q + 8) : z;
            float2 a3 = v1 ? *(const float2*)(rb + kc * 16 + q + 8) : z;
            split2(a0.x, a0.y, Ah[kc][0], Al[kc][0]);
            split2(a1.x, a1.y, Ah[kc][1], Al[kc][1]);
            split2(a2.x, a2.y, Ah[kc][2], Al[kc][2]);
            split2(a3.x, a3.y, Ah[kc][3], Al[kc][3]);
        }
    }

#pragma unroll 1
    for (int m = 0; m < 2; ++m) {
        if (m) __syncthreads();
        stage_u32(smw, m ? g_WQf : g_WPf, WPQ_U32);
        __syncthreads();
        float* dst = m ? g_Q : g_P;
#pragma unroll
        for (int hf = 0; hf < 2; ++hf) {
            float C[8][4];
#pragma unroll
            for (int t = 0; t < 8; ++t) { C[t][0] = C[t][1] = C[t][2] = C[t][3] = 0.f; }
#pragma unroll
            for (int kc = 0; kc < 8; ++kc)
#pragma unroll
                for (int t = 0; t < 8; ++t) {
                    int tt = hf * 8 + t;
                    uint2 bv = *(const uint2*)(smw + (((kc * 16 + tt) * 32 + l) * 2));
                    mma16816(C[t], Ah[kc], bv.x, bv.y);
                    mma16816(C[t], Al[kc], bv.x, bv.y);
                }
#pragma unroll
            for (int kc = 0; kc < 8; ++kc)
#pragma unroll
                for (int t = 0; t < 8; ++t) {
                    int tt = hf * 8 + t;
                    uint2 bv = *(const uint2*)(smw + ((((8 + kc) * 16 + tt) * 32 + l) * 2));
                    mma16816(C[t], Ah[kc], bv.x, bv.y);
                }
#pragma unroll
            for (int t = 0; t < 8; ++t) {
                int c = hf * 64 + t * 8 + q;
                if (v0) *(float2*)(dst + (size_t)r0 * 128 + c) = make_float2(C[t][0], C[t][1]);
                if (v1) *(float2*)(dst + (size_t)r1 * 128 + c) = make_float2(C[t][2], C[t][3]);
            }
        }
    }
}

// ---------------- kernel 3: edge (R14 design + dst-dedup atomics) -----------
#define EDGE_SMEM_B ((W1F_U32 + W2F_U32) * 4 + 384 * 4)
__global__ void __launch_bounds__(256, 2)
edge_kernel(const float* __restrict__ edge_attr,
            const float* __restrict__ bm1, const float* __restrict__ bm2) {
    extern __shared__ u32 smu[];
    u32* W1s = smu;
    u32* W2s = W1s + W1F_U32;
    int* ssrc = (int*)(W2s + W2F_U32);    // 128
    int* sdst = ssrc + 128;               // 128
    int* sord = sdst + 128;               // 128

    int w = TID >> 5, l = TID & 31;
    {
        stage_u32(W1s, g_W1f, W1F_U32);
        stage_u32(W2s, g_W2f, W2F_U32);
    }

    int g = l >> 2;
    int q = (l & 3) * 2;
    int r0 = w * 16 + g;
    int r1 = r0 + 8;

#pragma unroll 1
    for (int sub = 0; sub < 2; ++sub) {
        int base = blockIdx.x * 256 + sub * 128;
        if (sub) __syncthreads();          // protect index arrays before rewrite
        if (TID < 128) {
            ssrc[TID] = g_s_src[base + TID];
            sdst[TID] = g_s_dst[base + TID];
            sord[TID] = g_ord[base + TID];
        }
        __syncthreads();

        u32 Eh[2][4], El[2][4];
        {
            const float* ra = edge_attr + (size_t)sord[r0] * 32;
            const float* rb = edge_attr + (size_t)sord[r1] * 32;
#pragma unroll
            for (int kc = 0; kc < 2; ++kc) {
                float2 f0 = *(const float2*)(ra + kc * 16 + q);
                float2 f1 = *(const float2*)(rb + kc * 16 + q);
                float2 f2v = *(const float2*)(ra + kc * 16 + q + 8);
                float2 f3 = *(const float2*)(rb + kc * 16 + q + 8);
                split2(f0.x, f0.y, Eh[kc][0], El[kc][0]);
                split2(f1.x, f1.y, Eh[kc][1], El[kc][1]);
                split2(f2v.x, f2v.y, Eh[kc][2], El[kc][2]);
                split2(f3.x, f3.y, Eh[kc][3], El[kc][3]);
            }
        }

        float C[16][4];
        int s0 = ssrc[r0], s1 = ssrc[r1], d0 = sdst[r0], d1 = sdst[r1];
        const float* P0 = g_P + (size_t)s0 * 128;
        const float* P1 = g_P + (size_t)s1 * 128;
        const float* Q0 = g_Q + (size_t)d0 * 128;
        const float* Q1 = g_Q + (size_t)d1 * 128;
#pragma unroll
        for (int t = 0; t < 16; ++t) {
            int c = t * 8 + q;
            float2 b = *(const float2*)(bm1 + c);
            float2 p0 = *(const float2*)(P0 + c), q0 = *(const float2*)(Q0 + c);
            float2 p1 = *(const float2*)(P1 + c), q1 = *(const float2*)(Q1 + c);
            C[t][0] = p0.x + q0.x + b.x; C[t][1] = p0.y + q0.y + b.y;
            C[t][2] = p1.x + q1.x + b.x; C[t][3] = p1.y + q1.y + b.y;
        }

        // GEMM0 combined passes: W1h once -> (Eh, El); W1l once -> Eh
#pragma unroll
        for (int kc = 0; kc < 2; ++kc)
#pragma unroll
            for (int t = 0; t < 16; ++t) {
                uint2 bv = *(const uint2*)(W1s + (((kc * 16 + t) * 32 + l) * 2));
                mma16816(C[t], Eh[kc], bv.x, bv.y);
                mma16816(C[t], El[kc], bv.x, bv.y);
            }
#pragma unroll
        for (int kc = 0; kc < 2; ++kc)
#pragma unroll
            for (int t = 0; t < 16; ++t) {
                uint2 bv = *(const uint2*)(W1s + ((((2 + kc) * 16 + t) * 32 + l) * 2));
                mma16816(C[t], Eh[kc], bv.x, bv.y);
            }

        u32 Ah[8][4], Al[8][4];
#pragma unroll
        for (int kc = 0; kc < 8; ++kc) {
            split2(fmaxf(C[2 * kc][0], 0.f),     fmaxf(C[2 * kc][1], 0.f),     Ah[kc][0], Al[kc][0]);
            split2(fmaxf(C[2 * kc][2], 0.f),     fmaxf(C[2 * kc][3], 0.f),     Ah[kc][1], Al[kc][1]);
            split2(fmaxf(C[2 * kc + 1][0], 0.f), fmaxf(C[2 * kc + 1][1], 0.f), Ah[kc][2], Al[kc][2]);
            split2(fmaxf(C[2 * kc + 1][2], 0.f), fmaxf(C[2 * kc + 1][3], 0.f), Ah[kc][3], Al[kc][3]);
        }

        float* agg0 = g_agg + (size_t)d0 * 128;
        float* agg1 = g_agg + (size_t)d1 * 128;
        bool same_dst = (d0 == d1);
#pragma unroll
        for (int hf = 0; hf < 2; ++hf) {
            float C2[8][4];
#pragma unroll
            for (int t = 0; t < 8; ++t) {
                float2 b = *(const float2*)(bm2 + hf * 64 + t * 8 + q);
                C2[t][0] = b.x; C2[t][1] = b.y; C2[t][2] = b.x; C2[t][3] = b.y;
            }
            // GEMM1 combined passes: W2h once -> (Ah, Al); W2l once -> Ah
#pragma unroll
            for (int kc = 0; kc < 8; ++kc)
#pragma unroll
                for (int t = 0; t < 8; ++t) {
                    int tt = hf * 8 + t;
                    uint2 bv = *(const uint2*)(W2s + (((kc * 16 + tt) * 32 + l) * 2));
                    mma16816(C2[t], Ah[kc], bv.x, bv.y);
                    mma16816(C2[t], Al[kc], bv.x, bv.y);
                }
#pragma unroll
            for (int kc = 0; kc < 8; ++kc)
#pragma unroll
                for (int t = 0; t < 8; ++t) {
                    int tt = hf * 8 + t;
                    uint2 bv = *(const uint2*)(W2s + ((((8 + kc) * 16 + tt) * 32 + l) * 2));
                    mma16816(C2[t], Ah[kc], bv.x, bv.y);
                }
            // lane-pair merge (cols) + dst-dedup (rows): post-sort, rows r0/r1
            // often share dst; sum in registers and issue one red.v4.
#pragma unroll
            for (int t = 0; t < 8; ++t) {
                float a0 = fmaxf(C2[t][0], 0.f), a1 = fmaxf(C2[t][1], 0.f);
                float a2 = fmaxf(C2[t][2], 0.f), a3 = fmaxf(C2[t][3], 0.f);
                float p0 = __shfl_xor_sync(0xffffffffu, a0, 1);
                float p1 = __shfl_xor_sync(0xffffffffu, a1, 1);
                float p2 = __shfl_xor_sync(0xffffffffu, a2, 1);
                float p3 = __shfl_xor_sync(0xffffffffu, a3, 1);
                if (!(l & 1)) {
                    int c = hf * 64 + t * 8 + q;
                    if (same_dst) {
                        red_add_v4(agg0 + c, make_float4(a0 + a2, a1 + a3, p0 + p2, p1 + p3));
                    } else {
                        red_add_v4(agg0 + c, make_float4(a0, a1, p0, p1));
                        red_add_v4(agg1 + c, make_float4(a2, a3, p2, p3));
                    }
                }
            }
        }
    }
}

// ---------------- kernel 4: update (mma.sync, 64KB smem, occ 2) -------------
#define UPD2_SMEM (16384 * 4)
__global__ void __launch_bounds__(256, 2)
update_kernel(const float* __restrict__ h,
              const float* __restrict__ bu1, const float* __restrict__ bu2,
              float* __restrict__ out) {
    extern __shared__ u32 smw[];
    int w = TID >> 5, l = TID & 31;
    int base = blockIdx.x * 128;
    int g = l >> 2, q = (l & 3) * 2;
    int r0 = base + w * 16 + g, r1 = r0 + 8;
    bool v0 = r0 < NN, v1 = r1 < NN;

    float C[16][4];
#pragma unroll
    for (int t = 0; t < 16; ++t) {
        float2 b = *(const float2*)(bu1 + t * 8 + q);
        C[t][0] = b.x; C[t][1] = b.y; C[t][2] = b.x; C[t][3] = b.y;
    }

    stage_u32(smw, g_WU1f, 16384);
    __syncthreads();
#pragma unroll 1
    for (int ph = 0; ph < 2; ++ph) {
        const float* src = ph ? g_agg : h;
        u32 Ahp[8][4], Alp[8][4];
        {
            const float* ra = src + (size_t)r0 * 128;
            const float* rb = src + (size_t)r1 * 128;
            float2 z = make_float2(0.f, 0.f);
#pragma unroll
            for (int kc = 0; kc < 8; ++kc) {
                float2 a0 = v0 ? *(const float2*)(ra + kc * 16 + q) : z;
                float2 a1 = v1 ? *(const float2*)(rb + kc * 16 + q) : z;
                float2 a2 = v0 ? *(const float2*)(ra + kc * 16 + q + 8) : z;
                float2 a3 = v1 ? *(const float2*)(rb + kc * 16 + q + 8) : z;
                split2(a0.x, a0.y, Ahp[kc][0], Alp[kc][0]);
                split2(a1.x, a1.y, Ahp[kc][1], Alp[kc][1]);
                split2(a2.x, a2.y, Ahp[kc][2], Alp[kc][2]);
                split2(a3.x, a3.y, Ahp[kc][3], Alp[kc][3]);
            }
        }
#pragma unroll
        for (int kc = 0; kc < 8; ++kc)
#pragma unroll
            for (int t = 0; t < 16; ++t) {
                uint2 bv = *(const uint2*)(smw + ((((ph * 8 + kc) * 16 + t) * 32 + l) * 2));
                mma16816(C[t], Ahp[kc], bv.x, bv.y);
                mma16816(C[t], Alp[kc], bv.x, bv.y);
            }
    }
    __syncthreads();
    stage_u32(smw, g_WU1f + 16384, 16384);
    __syncthreads();
#pragma unroll 1
    for (int ph = 0; ph < 2; ++ph) {
        const float* src = ph ? g_agg : h;
        u32 Ahp[8][4];
        {
            const float* ra = src + (size_t)r0 * 128;
            const float* rb = src + (size_t)r1 * 128;
            float2 z = make_float2(0.f, 0.f);
#pragma unroll
            for (int kc = 0; kc < 8; ++kc) {
                float2 a0 = v0 ? *(const float2*)(ra + kc * 16 + q) : z;
                float2 a1 = v1 ? *(const float2*)(rb + kc * 16 + q) : z;
                float2 a2 = v0 ? *(const float2*)(ra + kc * 16 + q + 8) : z;
                float2 a3 = v1 ? *(const float2*)(rb + kc * 16 + q + 8) : z;
                u16 h0 = f2bf(a0.x), h1 = f2bf(a0.y);
                Ahp[kc][0] = (u32)h0 | ((u32)h1 << 16);
                h0 = f2bf(a1.x); h1 = f2bf(a1.y);
                Ahp[kc][1] = (u32)h0 | ((u32)h1 << 16);
                h0 = f2bf(a2.x); h1 = f2bf(a2.y);
                Ahp[kc][2] = (u32)h0 | ((u32)h1 << 16);
                h0 = f2bf(a3.x); h1 = f2bf(a3.y);
                Ahp[kc][3] = (u32)h0 | ((u32)h1 << 16);
            }
        }
#pragma unroll
        for (int kc = 0; kc < 8; ++kc)
#pragma unroll
            for (int t = 0; t < 16; ++t) {
                uint2 bv = *(const uint2*)(smw + ((((ph * 8 + kc) * 16 + t) * 32 + l) * 2));
                mma16816(C[t], Ahp[kc], bv.x, bv.y);
            }
    }

    u32 Ah[8][4], Al[8][4];
#pragma unroll
    for (int kc = 0; kc < 8; ++kc) {
        split2(fmaxf(C[2 * kc][0], 0.f),     fmaxf(C[2 * kc][1], 0.f),     Ah[kc][0], Al[kc][0]);
        split2(fmaxf(C[2 * kc][2], 0.f),     fmaxf(C[2 * kc][3], 0.f),     Ah[kc][1], Al[kc][1]);
        split2(fmaxf(C[2 * kc + 1][0], 0.f), fmaxf(C[2 * kc + 1][1], 0.f), Ah[kc][2], Al[kc][2]);
        split2(fmaxf(C[2 * kc + 1][2], 0.f), fmaxf(C[2 * kc + 1][3], 0.f), Ah[kc][3], Al[kc][3]);
    }
    __syncthreads();
    stage_u32(smw, g_WU2f, WU2_U32);
    __syncthreads();

#pragma unroll
    for (int hf = 0; hf < 2; ++hf) {
        float C2[8][4];
#pragma unroll
        for (int t = 0; t < 8; ++t) {
            float2 b = *(const float2*)(bu2 + hf * 64 + t * 8 + q);
            C2[t][0] = b.x; C2[t][1] = b.y; C2[t][2] = b.x; C2[t][3] = b.y;
        }
#pragma unroll
        for (int kc = 0; kc < 8; ++kc)
#pragma unroll
            for (int t = 0; t < 8; ++t) {
                int tt = hf * 8 + t;
                uint2 bv = *(const uint2*)(smw + (((kc * 16 + tt) * 32 + l) * 2));
                mma16816(C2[t], Ah[kc], bv.x, bv.y);
                mma16816(C2[t], Al[kc], bv.x, bv.y);
            }
#pragma unroll
        for (int kc = 0; kc < 8; ++kc)
#pragma unroll
            for (int t = 0; t < 8; ++t) {
                int tt = hf * 8 + t;
                uint2 bv = *(const uint2*)(smw + ((((8 + kc) * 16 + tt) * 32 + l) * 2));
                mma16816(C2[t], Ah[kc], bv.x, bv.y);
            }
#pragma unroll
        for (int t = 0; t < 8; ++t) {
            int c = hf * 64 + t * 8 + q;
            if (v0) {
                float2 hh = *(const float2*)(h + (size_t)r0 * 128 + c);
                *(float2*)(out + (size_t)r0 * 128 + c) = make_float2(hh.x + C2[t][0], hh.y + C2[t][1]);
            }
            if (v1) {
                float2 hh = *(const float2*)(h + (size_t)r1 * 128 + c);
                *(float2*)(out + (size_t)r1 * 128 + c) = make_float2(hh.x + C2[t][2], hh.y + C2[t][3]);
            }
        }
    }
}

// ---------------------------------------------------------------------------
extern "C" void kernel_launch(void* const* d_in, const int* in_sizes, int n_in,
                              void* d_out, int out_size) {
    const float* h         = (const float*)d_in[0];
    const float* edge_attr = (const float*)d_in[1];
    const float* Wm1       = (const float*)d_in[2];
    const float* bm1       = (const float*)d_in[3];
    const float* Wm2       = (const float*)d_in[4];
    const float* bm2       = (const float*)d_in[5];
    const float* Wu1       = (const float*)d_in[6];
    const float* bu1       = (const float*)d_in[7];
    const float* Wu2       = (const float*)d_in[8];
    const float* bu2       = (const float*)d_in[9];
    const void*  eidx      = (const void*)d_in[10];
    float* out             = (float*)d_out;

    cudaFuncSetAttribute(pq_scatter_kernel, cudaFuncAttributeMaxDynamicSharedMemorySize, PQ2_SMEM);
    cudaFuncSetAttribute(edge_kernel,       cudaFuncAttributeMaxDynamicSharedMemorySize, EDGE_SMEM_B);
    cudaFuncSetAttribute(update_kernel,     cudaFuncAttributeMaxDynamicSharedMemorySize, UPD2_SMEM);

    convprep_kernel<<<(EE + 255) / 256, 256>>>(eidx, Wm1, Wm2, Wu1, Wu2);  // idx 0
    scan_kernel<<<1, 1024>>>();                                            // idx 1
    pq_scatter_kernel<<<(EE + 255) / 256, 256, PQ2_SMEM>>>(h);             // idx 2
    edge_kernel<<<EE / 256, 256, EDGE_SMEM_B>>>(edge_attr, bm1, bm2);      // idx 3 (profiled)
    update_kernel<<<(NN + 127) / 128, 256, UPD2_SMEM>>>(h, bu1, bu2, out); // idx 4
}